// round 16
// baseline (speedup 1.0000x reference)
#include <cuda_runtime.h>
#include <cuda_fp16.h>
#include <cstdint>

#define N_NODES 100000
#define N_EDGES 500000
#define IN_DIM 16
#define HEADS 4
#define OUT_DIM 128
#define HC 512           // HEADS*OUT_DIM
#define NEG 0.2f

#define TILE_M 256       // edges per block-tile (8 warps x 32)
#define TS_THREADS 256
#define TS_GRID 296      // persistent; 2 blocks/SM
#define N_TILES ((N_EDGES + TILE_M - 1) / TILE_M)
#define BK 56            // padded K stride (halves) for conflict-free LDS
#define SMEM_TS (2048 + 512 * BK * 2)   // att[512] f32 + B[512][56] f16

#define SCAN_CHUNK 256
#define N_CHUNKS ((N_NODES + SCAN_CHUNK - 1) / SCAN_CHUNK)   // 391

#define AGG_NODES 64     // nodes per fused aggregate+outproj block
#define AGG_THREADS 256
#define N_AGG_BLOCKS ((N_NODES + AGG_NODES - 1) / AGG_NODES)
// smem: W packed u64 [16][256] = 32KB, y [64][64] f32 = 16KB, gate [64][4] = 1KB
#define SMEM_AGG (32768 + 16384 + 1024)

// Scratch (device globals: allocation-free per harness rules)
__device__ __half g_xf16[(size_t)N_NODES * IN_DIM];   // fp16 X, 3.2 MB (L2-resident)
__device__ float  g_ex[(size_t)N_EDGES * HEADS];      // 8 MB, [slot][h]
__device__ int    g_counts[N_NODES];
__device__ int    g_row[N_NODES + 1];
__device__ int    g_cursor[N_NODES];
__device__ int    g_chunksum[N_CHUNKS];               // inclusive chunk sums
__device__ int    g_srcs[N_EDGES];                    // CSR: src per slot
__device__ int    g_dsts[N_EDGES];                    // CSR: dst per slot

__device__ __forceinline__ float lrelu(float v) { return fmaxf(v, NEG * v); }

// packed f32x2 helpers
__device__ __forceinline__ unsigned long long pack2(float lo, float hi) {
    unsigned long long r;
    asm("mov.b64 %0, {%1, %2};" : "=l"(r) : "f"(lo), "f"(hi));
    return r;
}
__device__ __forceinline__ void unpack2(unsigned long long v, float& lo, float& hi) {
    asm("mov.b64 {%0, %1}, %2;" : "=f"(lo), "=f"(hi) : "l"(v));
}
__device__ __forceinline__ void ffma2(unsigned long long& d,
                                      unsigned long long a, unsigned long long b) {
    asm("fma.rn.f32x2 %0, %1, %2, %3;" : "=l"(d) : "l"(a), "l"(b), "l"(d));
}

// HMMA m16n8k16 row.col f32 = f16*f16 + f32 (sm_80+, legal on compute_103)
__device__ __forceinline__ void mma16816(float* c, const uint32_t* a,
                                         uint32_t b0, uint32_t b1) {
    asm volatile(
        "mma.sync.aligned.m16n8k16.row.col.f32.f16.f16.f32 "
        "{%0,%1,%2,%3}, {%4,%5,%6,%7}, {%8,%9}, {%0,%1,%2,%3};"
        : "+f"(c[0]), "+f"(c[1]), "+f"(c[2]), "+f"(c[3])
        : "r"(a[0]), "r"(a[1]), "r"(a[2]), "r"(a[3]), "r"(b0), "r"(b1));
}

// ---------------------------------------------------------------------------
// K0: X -> fp16 copy
// ---------------------------------------------------------------------------
__global__ __launch_bounds__(256) void xcvt_kernel(const float* __restrict__ X)
{
    const int i = blockIdx.x * blockDim.x + threadIdx.x;
    if (i < N_NODES * IN_DIM) g_xf16[i] = __float2half_rn(X[i]);
}

// ---------------------------------------------------------------------------
// CSR build: histogram -> PARALLEL 3-stage scan -> fill (unchanged)
// ---------------------------------------------------------------------------
__global__ __launch_bounds__(256) void hist_kernel(const int* __restrict__ idx)
{
    const int e = blockIdx.x * blockDim.x + threadIdx.x;
    if (e < N_EDGES) atomicAdd(&g_counts[idx[N_EDGES + e]], 1);
}

__global__ __launch_bounds__(SCAN_CHUNK) void scanA_kernel()
{
    __shared__ int sp[SCAN_CHUNK];
    const int gid = blockIdx.x * SCAN_CHUNK + threadIdx.x;
    sp[threadIdx.x] = (gid < N_NODES) ? g_counts[gid] : 0;
    __syncthreads();
    for (int off = SCAN_CHUNK / 2; off > 0; off >>= 1) {
        if (threadIdx.x < off) sp[threadIdx.x] += sp[threadIdx.x + off];
        __syncthreads();
    }
    if (threadIdx.x == 0) g_chunksum[blockIdx.x] = sp[0];
}

__global__ __launch_bounds__(512) void scanB_kernel()
{
    __shared__ int sp[512];
    const int t = threadIdx.x;
    sp[t] = (t < N_CHUNKS) ? g_chunksum[t] : 0;
    __syncthreads();
    for (int off = 1; off < 512; off <<= 1) {
        int v = (t >= off) ? sp[t - off] : 0;
        __syncthreads();
        sp[t] += v;
        __syncthreads();
    }
    if (t < N_CHUNKS) g_chunksum[t] = sp[t];   // inclusive
}

__global__ __launch_bounds__(SCAN_CHUNK) void scanC_kernel()
{
    __shared__ int sp[SCAN_CHUNK];
    const int t = threadIdx.x;
    const int gid = blockIdx.x * SCAN_CHUNK + t;
    const int c = (gid < N_NODES) ? g_counts[gid] : 0;
    sp[t] = c;
    __syncthreads();
    for (int off = 1; off < SCAN_CHUNK; off <<= 1) {
        int v = (t >= off) ? sp[t - off] : 0;
        __syncthreads();
        sp[t] += v;
        __syncthreads();
    }
    const int base = (blockIdx.x > 0) ? g_chunksum[blockIdx.x - 1] : 0;
    const int val = base + sp[t] - c;   // exclusive prefix
    if (gid < N_NODES) {
        g_row[gid] = val;
        g_cursor[gid] = val;
    }
    if (blockIdx.x == N_CHUNKS - 1 && t == SCAN_CHUNK - 1)
        g_row[N_NODES] = N_EDGES;
}

__global__ __launch_bounds__(256) void fill_kernel(const int* __restrict__ idx)
{
    const int e = blockIdx.x * blockDim.x + threadIdx.x;
    if (e >= N_EDGES) return;
    const int dst = idx[N_EDGES + e];
    const int pos = atomicAdd(&g_cursor[dst], 1);
    g_srcs[pos] = idx[e];
    g_dsts[pos] = dst;
}

// ---------------------------------------------------------------------------
// K2: tensor-core (HMMA) edge scores. 32 edges per warp. (unchanged from R14)
// ---------------------------------------------------------------------------
__global__ __launch_bounds__(TS_THREADS, 2) void tensor_score_kernel(
    const float* __restrict__ Wl, const float* __restrict__ bl,
    const float* __restrict__ Wr, const float* __restrict__ br,
    const float* __restrict__ att)
{
    extern __shared__ char dsm[];
    float* satt = (float*)dsm;                 // 512 f32
    __half* sB = (__half*)(dsm + 2048);        // [512][BK]

    const int tid = threadIdx.x;

    for (int i = tid; i < HC; i += TS_THREADS) satt[i] = att[i];
    for (int i = tid; i < 512 * BK; i += TS_THREADS) {
        const int n = i / BK, k = i % BK;
        float v = 0.f;
        if (k < 16)       v = Wl[k * HC + n];
        else if (k < 32)  v = Wr[(k - 16) * HC + n];
        else if (k == 32) v = bl[n] + br[n];
        sB[n * BK + k] = __float2half_rn(v);
    }
    __syncthreads();

    const int w = tid >> 5;
    const int lane = tid & 31;
    const int g = lane >> 2;   // row group (0..7)
    const int t4 = lane & 3;   // thread-in-quad

    uint32_t aC[4];
    aC[0] = (t4 == 0) ? 0x00003C00u : 0u;
    aC[1] = aC[0];
    aC[2] = 0u;
    aC[3] = 0u;

    for (int tile = blockIdx.x; tile < N_TILES; tile += gridDim.x) {
        const int e0 = tile * TILE_M + w * 32 + g;
        const int e1 = e0 + 8;
        const int e2 = e0 + 16;
        const int e3 = e0 + 24;

        int ec[4] = {e0, e1, e2, e3};
        uint32_t A[4][8];
#pragma unroll
        for (int p = 0; p < 2; p++) {
            const int elo = min(ec[2 * p],     N_EDGES - 1);
            const int ehi = min(ec[2 * p + 1], N_EDGES - 1);
            const int s_lo = __ldg(&g_srcs[elo]);
            const int s_hi = __ldg(&g_srcs[ehi]);
            const int d_lo = __ldg(&g_dsts[elo]);
            const int d_hi = __ldg(&g_dsts[ehi]);
            const uint32_t* xs_lo = (const uint32_t*)(g_xf16 + (size_t)s_lo * IN_DIM);
            const uint32_t* xs_hi = (const uint32_t*)(g_xf16 + (size_t)s_hi * IN_DIM);
            const uint32_t* xd_lo = (const uint32_t*)(g_xf16 + (size_t)d_lo * IN_DIM);
            const uint32_t* xd_hi = (const uint32_t*)(g_xf16 + (size_t)d_hi * IN_DIM);
            A[2 * p][0] = __ldg(&xs_lo[t4]);     A[2 * p][1] = __ldg(&xs_hi[t4]);
            A[2 * p][2] = __ldg(&xs_lo[t4 + 4]); A[2 * p][3] = __ldg(&xs_hi[t4 + 4]);
            A[2 * p + 1][0] = __ldg(&xd_lo[t4]);     A[2 * p + 1][1] = __ldg(&xd_hi[t4]);
            A[2 * p + 1][2] = __ldg(&xd_lo[t4 + 4]); A[2 * p + 1][3] = __ldg(&xd_hi[t4 + 4]);
        }

        float acc[4][HEADS];
#pragma unroll
        for (int r = 0; r < 4; r++)
#pragma unroll
            for (int h = 0; h < HEADS; h++) acc[r][h] = 0.f;

#pragma unroll 4
        for (int nt = 0; nt < 64; nt++) {
            const int h = nt >> 4;
            const __half* bp = sB + (nt * 8 + g) * BK + t4 * 2;
            const uint32_t b00 = *(const uint32_t*)(bp);
            const uint32_t b01 = *(const uint32_t*)(bp + 8);
            const uint32_t b10 = *(const uint32_t*)(bp + 16);
            const uint32_t b11 = *(const uint32_t*)(bp + 24);
            const uint32_t b20 = *(const uint32_t*)(bp + 32);
            const uint32_t b21 = *(const uint32_t*)(bp + 40);
            const float2 aw = *(const float2*)(satt + nt * 8 + t4 * 2);

#pragma unroll
            for (int p = 0; p < 2; p++) {
                float c[4] = {0.f, 0.f, 0.f, 0.f};
                mma16816(c, A[2 * p],     b00, b01);
                mma16816(c, A[2 * p + 1], b10, b11);
                mma16816(c, aC,           b20, b21);
                acc[2 * p][h]     = fmaf(lrelu(c[0]), aw.x,
                                    fmaf(lrelu(c[1]), aw.y, acc[2 * p][h]));
                acc[2 * p + 1][h] = fmaf(lrelu(c[2]), aw.x,
                                    fmaf(lrelu(c[3]), aw.y, acc[2 * p + 1][h]));
            }
        }

#pragma unroll
        for (int r = 0; r < 4; r++)
#pragma unroll
            for (int h = 0; h < HEADS; h++) {
                float v = acc[r][h];
                v += __shfl_xor_sync(0xffffffffu, v, 1);
                v += __shfl_xor_sync(0xffffffffu, v, 2);
                acc[r][h] = v;
            }

        if (t4 == 0) {
#pragma unroll
            for (int r = 0; r < 4; r++) {
                if (ec[r] < N_EDGES)
                    ((float4*)g_ex)[ec[r]] = make_float4(
                        __expf(acc[r][0]), __expf(acc[r][1]),
                        __expf(acc[r][2]), __expf(acc[r][3]));
            }
        }
    }
}

// ---------------------------------------------------------------------------
// K3 (fused): X-space aggregation + output projection in one kernel.
// Block = 256 threads / 64 nodes.
//  Phase 1: each warp aggregates 8 nodes (identical loop to R14 aggregate,
//           lane-parallel src preload), writes normalized y + gate to SMEM.
//  Phase 2: thread = 2 output columns; out = y@W_l + gate*b_l + bias, with
//           W_l staged once per block in SMEM as packed u64 (ffma2 path).
// Removes the 51 MB g_y/g_gate global round-trip and one kernel launch.
// ---------------------------------------------------------------------------
__global__ __launch_bounds__(AGG_THREADS) void aggproj_kernel(
    const float* __restrict__ X,
    const float* __restrict__ Wl, const float* __restrict__ bl,
    const float* __restrict__ bias, float* __restrict__ out)
{
    extern __shared__ char sm[];
    unsigned long long* sw = (unsigned long long*)sm;          // [16][256] u64
    float* sy    = (float*)(sm + 32768);                       // [64][64]
    float* sgate = (float*)(sm + 32768 + 16384);               // [64][4]

    const int tid = threadIdx.x;
    const int w = tid >> 5;
    const int lane = tid & 31;
    const unsigned FULL = 0xffffffffu;

    // stage W_l packed (coalesced: thread i loads columns 2i, 2i+1 per k)
    for (int k = 0; k < IN_DIM; k++)
        sw[k * 256 + tid] = pack2(Wl[k * HC + 2 * tid], Wl[k * HC + 2 * tid + 1]);

    // ---- phase 1: aggregate 8 nodes per warp ----
    const int k16 = lane & 15;
    const int half = lane >> 4;

    for (int i = 0; i < 8; i++) {
        const int nl = w * 8 + i;                 // node-local 0..63
        const int node = blockIdx.x * AGG_NODES + nl;
        if (node >= N_NODES) break;

        const int eb = g_row[node];
        const int ee = g_row[node + 1];

        float yA = 0.f, yB = 0.f;
        float4 den = make_float4(0.f, 0.f, 0.f, 0.f);

        for (int b = eb; b < ee; b += 32) {
            const int cnt = min(32, ee - b);
            int li = b + lane;
            if (li >= ee) li = eb;
            const int my_src = g_srcs[li];        // lane-parallel preload

            for (int j = 0; j < cnt; j++) {
                const int src = __shfl_sync(FULL, my_src, j);
                const float4 ex = __ldg(&((const float4*)g_ex)[b + j]);
                const float xv = __ldg(&X[(size_t)src * IN_DIM + k16]);
                const float wA = half ? ex.y : ex.x;
                const float wB = half ? ex.w : ex.z;
                yA = fmaf(wA, xv, yA);
                yB = fmaf(wB, xv, yB);
                den.x += ex.x; den.y += ex.y; den.z += ex.z; den.w += ex.w;
            }
        }

        const float dA = half ? den.y : den.x;
        const float dB = half ? den.w : den.z;
        const float iA = (dA > 0.f) ? (1.0f / dA) : 0.f;
        const float iB = (dB > 0.f) ? (1.0f / dB) : 0.f;

        sy[nl * 64 + lane]      = yA * iA;
        sy[nl * 64 + 32 + lane] = yB * iB;
        if (lane < 4) {
            const float d = (lane == 0) ? den.x : (lane == 1) ? den.y
                          : (lane == 2) ? den.z : den.w;
            sgate[nl * 4 + lane] = (d > 0.f) ? 1.f : 0.f;
        }
    }
    __syncthreads();

    // ---- phase 2: outproj (thread = 2 adjacent columns) ----
    const int c0 = tid * 2;
    const int hh = c0 >> 7;

    unsigned long long wreg[IN_DIM];
#pragma unroll
    for (int k = 0; k < IN_DIM; k++) wreg[k] = sw[k * 256 + tid];
    const float bl0 = bl[c0], bl1 = bl[c0 + 1];
    const float bs0 = bias[c0], bs1 = bias[c0 + 1];

    const int n0 = blockIdx.x * AGG_NODES;
    const int nmax = min(AGG_NODES, N_NODES - n0);

    for (int n = 0; n < nmax; n++) {
        const float gate = sgate[n * 4 + hh];
        unsigned long long acc = pack2(fmaf(gate, bl0, bs0), fmaf(gate, bl1, bs1));
        const float* yrow = sy + n * 64 + hh * 16;
#pragma unroll
        for (int k = 0; k < IN_DIM; k++) {
            const float yv = yrow[k];
            ffma2(acc, pack2(yv, yv), wreg[k]);
        }
        float o0, o1;
        unpack2(acc, o0, o1);
        ((float2*)out)[((size_t)(n0 + n) * HC + c0) >> 1] = make_float2(o0, o1);
    }
}

// ---------------------------------------------------------------------------
extern "C" void kernel_launch(void* const* d_in, const int* in_sizes, int n_in,
                              void* d_out, int out_size)
{
    const float* X    = (const float*)d_in[0];  // [N, 16]
    const int*   idx  = (const int*)  d_in[1];  // [2, E]
    const float* Wl   = (const float*)d_in[2];  // [16, 512]
    const float* bl   = (const float*)d_in[3];  // [512]
    const float* Wr   = (const float*)d_in[4];  // [16, 512]
    const float* br   = (const float*)d_in[5];  // [512]
    const float* att  = (const float*)d_in[6];  // [4, 128]
    const float* bias = (const float*)d_in[7];  // [512]
    float* out = (float*)d_out;                 // [N, 512]

    void* counts_ptr = nullptr;
    cudaGetSymbolAddress(&counts_ptr, g_counts);
    cudaMemsetAsync(counts_ptr, 0, N_NODES * sizeof(int), 0);

    cudaFuncSetAttribute(tensor_score_kernel,
                         cudaFuncAttributeMaxDynamicSharedMemorySize, SMEM_TS);
    cudaFuncSetAttribute(aggproj_kernel,
                         cudaFuncAttributeMaxDynamicSharedMemorySize, SMEM_AGG);

    xcvt_kernel<<<(N_NODES * IN_DIM + 255) / 256, 256>>>(X);
    hist_kernel<<<(N_EDGES + 255) / 256, 256>>>(idx);
    scanA_kernel<<<N_CHUNKS, SCAN_CHUNK>>>();
    scanB_kernel<<<1, 512>>>();
    scanC_kernel<<<N_CHUNKS, SCAN_CHUNK>>>();
    fill_kernel<<<(N_EDGES + 255) / 256, 256>>>(idx);
    tensor_score_kernel<<<TS_GRID, TS_THREADS, SMEM_TS>>>(Wl, bl, Wr, br, att);
    aggproj_kernel<<<N_AGG_BLOCKS, AGG_THREADS, SMEM_AGG>>>(X, Wl, bl, bias, out);
}

// round 17
// speedup vs baseline: 1.0284x; 1.0284x over previous
#include <cuda_runtime.h>
#include <cuda_fp16.h>
#include <cstdint>

#define N_NODES 100000
#define N_EDGES 500000
#define IN_DIM 16
#define HEADS 4
#define OUT_DIM 128
#define HC 512           // HEADS*OUT_DIM
#define NEG 0.2f

#define TILE_M 256       // edges per block-tile (8 warps x 32)
#define TS_THREADS 256
#define TS_GRID 296      // persistent; 2 blocks/SM
#define N_TILES ((N_EDGES + TILE_M - 1) / TILE_M)
#define BK 56            // padded K stride (halves) for conflict-free LDS
#define SMEM_TS (2048 + 512 * BK * 2)   // att[512] f32 + B[512][56] f16

#define SCAN_CHUNK 256
#define N_CHUNKS ((N_NODES + SCAN_CHUNK - 1) / SCAN_CHUNK)   // 391

#define XCVT_ELEMS (N_NODES * IN_DIM)   // 1.6M

// Scratch (device globals: allocation-free per harness rules)
__device__ __half g_xf16[(size_t)N_NODES * IN_DIM];   // fp16 X, 3.2 MB (L2-resident)
__device__ float  g_ex[(size_t)N_EDGES * HEADS];      // 8 MB, [slot][h]
__device__ float  g_y[(size_t)N_NODES * 64];          // normalized alpha-weighted X sums
__device__ float  g_gate[(size_t)N_NODES * HEADS];
__device__ int    g_counts[N_NODES];
__device__ int    g_row[N_NODES + 1];
__device__ int    g_cursor[N_NODES];
__device__ int    g_chunksum[N_CHUNKS];               // per-chunk sums (NOT scanned)
__device__ int    g_srcs[N_EDGES];                    // CSR: src per slot
__device__ int    g_dsts[N_EDGES];                    // CSR: dst per slot

__device__ __forceinline__ float lrelu(float v) { return fmaxf(v, NEG * v); }

// packed f32x2 helpers
__device__ __forceinline__ unsigned long long pack2(float lo, float hi) {
    unsigned long long r;
    asm("mov.b64 %0, {%1, %2};" : "=l"(r) : "f"(lo), "f"(hi));
    return r;
}
__device__ __forceinline__ void unpack2(unsigned long long v, float& lo, float& hi) {
    asm("mov.b64 {%0, %1}, %2;" : "=f"(lo), "=f"(hi) : "l"(v));
}
__device__ __forceinline__ void ffma2(unsigned long long& d,
                                      unsigned long long a, unsigned long long b) {
    asm("fma.rn.f32x2 %0, %1, %2, %3;" : "=l"(d) : "l"(a), "l"(b), "l"(d));
}

// HMMA m16n8k16 row.col f32 = f16*f16 + f32 (sm_80+, legal on compute_103)
__device__ __forceinline__ void mma16816(float* c, const uint32_t* a,
                                         uint32_t b0, uint32_t b1) {
    asm volatile(
        "mma.sync.aligned.m16n8k16.row.col.f32.f16.f16.f32 "
        "{%0,%1,%2,%3}, {%4,%5,%6,%7}, {%8,%9}, {%0,%1,%2,%3};"
        : "+f"(c[0]), "+f"(c[1]), "+f"(c[2]), "+f"(c[3])
        : "r"(a[0]), "r"(a[1]), "r"(a[2]), "r"(a[3]), "r"(b0), "r"(b1));
}

// ---------------------------------------------------------------------------
// K1 (fused): X->fp16 convert + dst histogram in one launch.
// Grid covers 1.6M xcvt elements; first 500k threads also do the hist atomic.
// ---------------------------------------------------------------------------
__global__ __launch_bounds__(256) void xcvt_hist_kernel(
    const float* __restrict__ X, const int* __restrict__ idx)
{
    const int i = blockIdx.x * blockDim.x + threadIdx.x;
    if (i < XCVT_ELEMS) g_xf16[i] = __float2half_rn(X[i]);
    if (i < N_EDGES) atomicAdd(&g_counts[idx[N_EDGES + i]], 1);
}

// ---------------------------------------------------------------------------
// CSR build: chunk sums -> self-basing scan (scanB eliminated) -> fill
// ---------------------------------------------------------------------------
__global__ __launch_bounds__(SCAN_CHUNK) void scanA_kernel()
{
    __shared__ int sp[SCAN_CHUNK];
    const int gid = blockIdx.x * SCAN_CHUNK + threadIdx.x;
    sp[threadIdx.x] = (gid < N_NODES) ? g_counts[gid] : 0;
    __syncthreads();
    for (int off = SCAN_CHUNK / 2; off > 0; off >>= 1) {
        if (threadIdx.x < off) sp[threadIdx.x] += sp[threadIdx.x + off];
        __syncthreads();
    }
    if (threadIdx.x == 0) g_chunksum[blockIdx.x] = sp[0];
}

// scanC: each block computes its own base (sum of prior chunk sums, <=391
// L2-resident ints) via block reduce, then the in-chunk exclusive scan.
__global__ __launch_bounds__(SCAN_CHUNK) void scanC_kernel()
{
    __shared__ int sp[SCAN_CHUNK];
    __shared__ int sbase;
    const int t = threadIdx.x;

    // block-reduce prior chunk sums
    int part = 0;
    for (int i = t; i < blockIdx.x; i += SCAN_CHUNK) part += g_chunksum[i];
    sp[t] = part;
    __syncthreads();
    for (int off = SCAN_CHUNK / 2; off > 0; off >>= 1) {
        if (t < off) sp[t] += sp[t + off];
        __syncthreads();
    }
    if (t == 0) sbase = sp[0];
    __syncthreads();
    const int base = sbase;
    __syncthreads();

    // in-chunk exclusive scan
    const int gid = blockIdx.x * SCAN_CHUNK + t;
    const int c = (gid < N_NODES) ? g_counts[gid] : 0;
    sp[t] = c;
    __syncthreads();
    for (int off = 1; off < SCAN_CHUNK; off <<= 1) {
        int v = (t >= off) ? sp[t - off] : 0;
        __syncthreads();
        sp[t] += v;
        __syncthreads();
    }
    const int val = base + sp[t] - c;   // exclusive prefix
    if (gid < N_NODES) {
        g_row[gid] = val;
        g_cursor[gid] = val;
    }
    if (blockIdx.x == N_CHUNKS - 1 && t == SCAN_CHUNK - 1)
        g_row[N_NODES] = N_EDGES;
}

__global__ __launch_bounds__(256) void fill_kernel(const int* __restrict__ idx)
{
    const int e = blockIdx.x * blockDim.x + threadIdx.x;
    if (e >= N_EDGES) return;
    const int dst = idx[N_EDGES + e];
    const int pos = atomicAdd(&g_cursor[dst], 1);
    g_srcs[pos] = idx[e];
    g_dsts[pos] = dst;
}

// ---------------------------------------------------------------------------
// K2: tensor-core (HMMA) edge scores. 32 edges per warp. (unchanged from R14)
// ---------------------------------------------------------------------------
__global__ __launch_bounds__(TS_THREADS, 2) void tensor_score_kernel(
    const float* __restrict__ Wl, const float* __restrict__ bl,
    const float* __restrict__ Wr, const float* __restrict__ br,
    const float* __restrict__ att)
{
    extern __shared__ char dsm[];
    float* satt = (float*)dsm;                 // 512 f32
    __half* sB = (__half*)(dsm + 2048);        // [512][BK]

    const int tid = threadIdx.x;

    for (int i = tid; i < HC; i += TS_THREADS) satt[i] = att[i];
    for (int i = tid; i < 512 * BK; i += TS_THREADS) {
        const int n = i / BK, k = i % BK;
        float v = 0.f;
        if (k < 16)       v = Wl[k * HC + n];
        else if (k < 32)  v = Wr[(k - 16) * HC + n];
        else if (k == 32) v = bl[n] + br[n];
        sB[n * BK + k] = __float2half_rn(v);
    }
    __syncthreads();

    const int w = tid >> 5;
    const int lane = tid & 31;
    const int g = lane >> 2;   // row group (0..7)
    const int t4 = lane & 3;   // thread-in-quad

    uint32_t aC[4];
    aC[0] = (t4 == 0) ? 0x00003C00u : 0u;
    aC[1] = aC[0];
    aC[2] = 0u;
    aC[3] = 0u;

    for (int tile = blockIdx.x; tile < N_TILES; tile += gridDim.x) {
        const int e0 = tile * TILE_M + w * 32 + g;
        const int e1 = e0 + 8;
        const int e2 = e0 + 16;
        const int e3 = e0 + 24;

        int ec[4] = {e0, e1, e2, e3};
        uint32_t A[4][8];
#pragma unroll
        for (int p = 0; p < 2; p++) {
            const int elo = min(ec[2 * p],     N_EDGES - 1);
            const int ehi = min(ec[2 * p + 1], N_EDGES - 1);
            const int s_lo = __ldg(&g_srcs[elo]);
            const int s_hi = __ldg(&g_srcs[ehi]);
            const int d_lo = __ldg(&g_dsts[elo]);
            const int d_hi = __ldg(&g_dsts[ehi]);
            const uint32_t* xs_lo = (const uint32_t*)(g_xf16 + (size_t)s_lo * IN_DIM);
            const uint32_t* xs_hi = (const uint32_t*)(g_xf16 + (size_t)s_hi * IN_DIM);
            const uint32_t* xd_lo = (const uint32_t*)(g_xf16 + (size_t)d_lo * IN_DIM);
            const uint32_t* xd_hi = (const uint32_t*)(g_xf16 + (size_t)d_hi * IN_DIM);
            A[2 * p][0] = __ldg(&xs_lo[t4]);     A[2 * p][1] = __ldg(&xs_hi[t4]);
            A[2 * p][2] = __ldg(&xs_lo[t4 + 4]); A[2 * p][3] = __ldg(&xs_hi[t4 + 4]);
            A[2 * p + 1][0] = __ldg(&xd_lo[t4]);     A[2 * p + 1][1] = __ldg(&xd_hi[t4]);
            A[2 * p + 1][2] = __ldg(&xd_lo[t4 + 4]); A[2 * p + 1][3] = __ldg(&xd_hi[t4 + 4]);
        }

        float acc[4][HEADS];
#pragma unroll
        for (int r = 0; r < 4; r++)
#pragma unroll
            for (int h = 0; h < HEADS; h++) acc[r][h] = 0.f;

#pragma unroll 4
        for (int nt = 0; nt < 64; nt++) {
            const int h = nt >> 4;
            const __half* bp = sB + (nt * 8 + g) * BK + t4 * 2;
            const uint32_t b00 = *(const uint32_t*)(bp);
            const uint32_t b01 = *(const uint32_t*)(bp + 8);
            const uint32_t b10 = *(const uint32_t*)(bp + 16);
            const uint32_t b11 = *(const uint32_t*)(bp + 24);
            const uint32_t b20 = *(const uint32_t*)(bp + 32);
            const uint32_t b21 = *(const uint32_t*)(bp + 40);
            const float2 aw = *(const float2*)(satt + nt * 8 + t4 * 2);

#pragma unroll
            for (int p = 0; p < 2; p++) {
                float c[4] = {0.f, 0.f, 0.f, 0.f};
                mma16816(c, A[2 * p],     b00, b01);
                mma16816(c, A[2 * p + 1], b10, b11);
                mma16816(c, aC,           b20, b21);
                acc[2 * p][h]     = fmaf(lrelu(c[0]), aw.x,
                                    fmaf(lrelu(c[1]), aw.y, acc[2 * p][h]));
                acc[2 * p + 1][h] = fmaf(lrelu(c[2]), aw.x,
                                    fmaf(lrelu(c[3]), aw.y, acc[2 * p + 1][h]));
            }
        }

#pragma unroll
        for (int r = 0; r < 4; r++)
#pragma unroll
            for (int h = 0; h < HEADS; h++) {
                float v = acc[r][h];
                v += __shfl_xor_sync(0xffffffffu, v, 1);
                v += __shfl_xor_sync(0xffffffffu, v, 2);
                acc[r][h] = v;
            }

        if (t4 == 0) {
#pragma unroll
            for (int r = 0; r < 4; r++) {
                if (ec[r] < N_EDGES)
                    ((float4*)g_ex)[ec[r]] = make_float4(
                        __expf(acc[r][0]), __expf(acc[r][1]),
                        __expf(acc[r][2]), __expf(acc[r][3]));
            }
        }
    }
}

// ---------------------------------------------------------------------------
// K3: X-space aggregation. One warp per node; srcs batch-preloaded
// lane-parallel + shfl broadcast. (unchanged from R14)
// ---------------------------------------------------------------------------
__global__ __launch_bounds__(256) void aggregate_kernel(const float* __restrict__ X)
{
    const int node = blockIdx.x * 8 + (threadIdx.x >> 5);
    if (node >= N_NODES) return;
    const int lane = threadIdx.x & 31;
    const int k = lane & 15;
    const int half = lane >> 4;
    const unsigned FULL = 0xffffffffu;

    const int eb = g_row[node];
    const int ee = g_row[node + 1];

    float yA = 0.f, yB = 0.f;             // heads: half and 2+half
    float4 den = make_float4(0.f, 0.f, 0.f, 0.f);

    for (int b = eb; b < ee; b += 32) {
        const int cnt = min(32, ee - b);
        int li = b + lane;
        if (li >= ee) li = eb;
        const int my_src = g_srcs[li];    // lane-parallel preload

        for (int j = 0; j < cnt; j++) {
            const int src = __shfl_sync(FULL, my_src, j);
            const float4 ex = __ldg(&((const float4*)g_ex)[b + j]);
            const float xv = __ldg(&X[(size_t)src * IN_DIM + k]);
            const float wA = half ? ex.y : ex.x;
            const float wB = half ? ex.w : ex.z;
            yA = fmaf(wA, xv, yA);
            yB = fmaf(wB, xv, yB);
            den.x += ex.x; den.y += ex.y; den.z += ex.z; den.w += ex.w;
        }
    }

    const float dA = half ? den.y : den.x;
    const float dB = half ? den.w : den.z;
    const float iA = (dA > 0.f) ? (1.0f / dA) : 0.f;
    const float iB = (dB > 0.f) ? (1.0f / dB) : 0.f;

    g_y[(size_t)node * 64 + lane]      = yA * iA;
    g_y[(size_t)node * 64 + 32 + lane] = yB * iB;
    if (lane < 4) {
        const float d = (lane == 0) ? den.x : (lane == 1) ? den.y
                      : (lane == 2) ? den.z : den.w;
        g_gate[node * HEADS + lane] = (d > 0.f) ? 1.f : 0.f;
    }
}

// ---------------------------------------------------------------------------
// K4: out[node] = y_norm[node] @ W_l + gate*b_l + bias. (unchanged from R14)
// ---------------------------------------------------------------------------
__global__ __launch_bounds__(256) void outproj_kernel(
    const float* __restrict__ Wl, const float* __restrict__ bl,
    const float* __restrict__ bias, float* __restrict__ out)
{
    __shared__ float sy[128 * 64];   // 32 KB
    __shared__ float sg[128 * HEADS];
    const int c0 = threadIdx.x * 2;
    const int hh = c0 >> 7;

    unsigned long long w[IN_DIM];
#pragma unroll
    for (int k = 0; k < IN_DIM; k++)
        w[k] = pack2(Wl[k * HC + c0], Wl[k * HC + c0 + 1]);
    const float bl0 = bl[c0], bl1 = bl[c0 + 1];
    const float bs0 = bias[c0], bs1 = bias[c0 + 1];

    const int n0 = blockIdx.x * 128;
    const int nmax = min(128, N_NODES - n0);

    for (int i = threadIdx.x; i < nmax * 64; i += blockDim.x)
        sy[i] = g_y[(size_t)n0 * 64 + i];
    for (int i = threadIdx.x; i < nmax * HEADS; i += blockDim.x)
        sg[i] = g_gate[n0 * HEADS + i];
    __syncthreads();

    for (int n = 0; n < nmax; n++) {
        const float gate = sg[n * HEADS + hh];
        unsigned long long acc = pack2(fmaf(gate, bl0, bs0), fmaf(gate, bl1, bs1));
        const float* yrow = sy + n * 64 + hh * 16;
#pragma unroll
        for (int k = 0; k < IN_DIM; k++) {
            const float yv = yrow[k];
            ffma2(acc, pack2(yv, yv), w[k]);
        }
        float o0, o1;
        unpack2(acc, o0, o1);
        ((float2*)out)[((size_t)(n0 + n) * HC + c0) >> 1] = make_float2(o0, o1);
    }
}

// ---------------------------------------------------------------------------
extern "C" void kernel_launch(void* const* d_in, const int* in_sizes, int n_in,
                              void* d_out, int out_size)
{
    const float* X    = (const float*)d_in[0];  // [N, 16]
    const int*   idx  = (const int*)  d_in[1];  // [2, E]
    const float* Wl   = (const float*)d_in[2];  // [16, 512]
    const float* bl   = (const float*)d_in[3];  // [512]
    const float* Wr   = (const float*)d_in[4];  // [16, 512]
    const float* br   = (const float*)d_in[5];  // [512]
    const float* att  = (const float*)d_in[6];  // [4, 128]
    const float* bias = (const float*)d_in[7];  // [512]
    float* out = (float*)d_out;                 // [N, 512]

    void* counts_ptr = nullptr;
    cudaGetSymbolAddress(&counts_ptr, g_counts);
    cudaMemsetAsync(counts_ptr, 0, N_NODES * sizeof(int), 0);

    cudaFuncSetAttribute(tensor_score_kernel,
                         cudaFuncAttributeMaxDynamicSharedMemorySize, SMEM_TS);

    xcvt_hist_kernel<<<(XCVT_ELEMS + 255) / 256, 256>>>(X, idx);
    scanA_kernel<<<N_CHUNKS, SCAN_CHUNK>>>();
    scanC_kernel<<<N_CHUNKS, SCAN_CHUNK>>>();
    fill_kernel<<<(N_EDGES + 255) / 256, 256>>>(idx);
    tensor_score_kernel<<<TS_GRID, TS_THREADS, SMEM_TS>>>(Wl, bl, Wr, br, att);
    aggregate_kernel<<<(N_NODES + 7) / 8, 256>>>(X);
    outproj_kernel<<<(N_NODES + 127) / 128, 256>>>(Wl, bl, bias, out);
}